// round 3
// baseline (speedup 1.0000x reference)
#include <cuda_runtime.h>
#include <stdint.h>

// SpikeFP32Floor, round 3: float4 + MLP=4 + REDUX-OR group packing.
//
// Input: 2048*1024 fp32 values, each unpacked MSB-first into 32 floats
// (0.0/1.0). Output: same unpacking of floor(value), bit-exact vs reference.
//
// Warp layout per 32-quad batch: lane L loads a float4 (16B); a batch covers
// 512B = 4 values. group g = L/8 selects the value, slot s = L%8 selects bit
// offsets 4s..4s+3 (MSB-first). Nibble is shifted to 28-4s and OR-reduced
// across the 8-lane group with ONE __reduce_or_sync (mask 0xFF<<8g) instead
// of 3 dependent shfl_xor. Floor is branchless. 4 bits -> float4 -> STG.128.
//
// Each thread processes FOUR batches (4x LDG.128 front-batched, MLP=4).

__device__ __forceinline__ unsigned quad_nib(float4 v) {
    // 1.0f = 0x3F800000 (bit 29 set), 0.0f = 0.
    unsigned n;
    n  = (__float_as_uint(v.x) >> 26) & 8u;   // offset 4s   -> nib bit 3
    n |= (__float_as_uint(v.y) >> 27) & 4u;   // offset 4s+1 -> nib bit 2
    n |= (__float_as_uint(v.z) >> 28) & 2u;   // offset 4s+2 -> nib bit 1
    n |= (__float_as_uint(v.w) >> 29) & 1u;   // offset 4s+3 -> nib bit 0
    return n;
}

__device__ __forceinline__ unsigned floor_bits(unsigned u) {
    // Branchless bit-level floor matching the reference:
    //   e >= 150 -> u unchanged (shc=0 -> mask=0)
    //   127 <= e < 150 -> clear low (150-e) mantissa bits; if negative with
    //                     fractional bits set, exact fp32 t - 1.0f
    //   e < 127 -> sign ? bits(-1.0f) : +0
    unsigned sgn = u & 0x80000000u;
    unsigned e   = (u >> 23) & 0xFFu;
    int d = 150 - (int)e;
    unsigned shc  = (unsigned)max(0, min(d, 23));
    unsigned mask = (1u << shc) - 1u;
    unsigned t    = u & ~mask;
    bool hasfrac  = (u & mask) != 0u;
    unsigned tm1  = __float_as_uint(__uint_as_float(t) - 1.0f);
    unsigned r    = (sgn && hasfrac) ? tm1 : t;
    if (e < 127u) r = sgn ? 0xBF800000u : 0u;
    return r;
}

__device__ __forceinline__ float4 unpack_nib(unsigned r, unsigned sh) {
    unsigned no = r >> sh;
    float4 o;
    o.x = (no & 8u) ? 1.0f : 0.0f;
    o.y = (no & 4u) ? 1.0f : 0.0f;
    o.z = (no & 2u) ? 1.0f : 0.0f;
    o.w = (no & 1u) ? 1.0f : 0.0f;
    return o;
}

__global__ void __launch_bounds__(256)
spike_floor_v5(const float4* __restrict__ x, float4* __restrict__ out,
               unsigned int nquads)
{
    unsigned tid  = blockIdx.x * blockDim.x + threadIdx.x;
    unsigned lane = threadIdx.x & 31u;
    unsigned warp = tid >> 5;

    size_t base = (size_t)warp * 128u;         // 128 quads per warp (4/thread)
    if (base + 128u > (size_t)nquads) return;  // warp-uniform guard

    size_t q0 = base + lane;

    // Front-batched loads (MLP=4 per lane).
    float4 a = __ldcs(&x[q0]);
    float4 b = __ldcs(&x[q0 + 32u]);
    float4 c = __ldcs(&x[q0 + 64u]);
    float4 d = __ldcs(&x[q0 + 96u]);

    unsigned sh    = 28u - 4u * (lane & 7u);
    unsigned gmask = 0xFFu << (lane & 24u);    // 8-lane group mask

    unsigned wa = __reduce_or_sync(gmask, quad_nib(a) << sh);
    unsigned wb = __reduce_or_sync(gmask, quad_nib(b) << sh);
    unsigned wc = __reduce_or_sync(gmask, quad_nib(c) << sh);
    unsigned wd = __reduce_or_sync(gmask, quad_nib(d) << sh);

    float4 oa = unpack_nib(floor_bits(wa), sh);
    float4 ob = unpack_nib(floor_bits(wb), sh);
    float4 oc = unpack_nib(floor_bits(wc), sh);
    float4 od = unpack_nib(floor_bits(wd), sh);

    __stcs(&out[q0],       oa);
    __stcs(&out[q0 + 32u], ob);
    __stcs(&out[q0 + 64u], oc);
    __stcs(&out[q0 + 96u], od);
}

extern "C" void kernel_launch(void* const* d_in, const int* in_sizes, int n_in,
                              void* d_out, int out_size)
{
    const float4* x   = (const float4*)d_in[0];
    float4*       out = (float4*)d_out;

    unsigned n_elems = (unsigned)in_sizes[0];   // 2048*1024*32 floats
    unsigned nquads  = n_elems >> 2;            // float4 count
    unsigned threads_total = nquads >> 2;       // 4 quads per thread

    const int threads = 256;
    unsigned blocks = (threads_total + threads - 1) / threads;

    spike_floor_v5<<<blocks, threads>>>(x, out, nquads);
}